// round 1
// baseline (speedup 1.0000x reference)
#include <cuda_runtime.h>
#include <cstdint>

// Problem constants
#define T_TOK 8192      // B*S tokens
#define DIM   1024      // D
#define HID   2048      // H
#define NE    8         // experts
#define TOPK  2

// GEMM tiling
#define BM 64
#define BN 64
#define BK 16
#define RCAP (T_TOK*TOPK + NE*BM)   // 16896: routed rows, per-expert padded to BM

// ---------------- device scratch (static: no allocations allowed) ----------------
__device__ int   g_cnt[NE];
__device__ int   g_cur[NE];
__device__ int   g_off[NE + 1];
__device__ int   g_tope[T_TOK * TOPK];
__device__ float g_topp[T_TOK * TOPK];
__device__ int   g_rowtok[RCAP];
__device__ float g_roww[RCAP];
__device__ float g_X[RCAP * DIM];          // gathered activations  (~66 MB)
__device__ float g_S[RCAP * HID];          // swiglu intermediate   (~132 MB)

// ---------------- packed f32x2 helpers (Blackwell FFMA2) ----------------
__device__ __forceinline__ unsigned long long pack2(float v) {
    unsigned int u = __float_as_uint(v);
    unsigned long long r;
    asm("mov.b64 %0, {%1, %1};" : "=l"(r) : "r"(u));
    return r;
}
__device__ __forceinline__ unsigned long long fma2(unsigned long long a,
                                                   unsigned long long b,
                                                   unsigned long long c) {
    unsigned long long d;
    asm("fma.rn.f32x2 %0, %1, %2, %3;" : "=l"(d) : "l"(a), "l"(b), "l"(c));
    return d;
}
__device__ __forceinline__ float2 unpack2(unsigned long long v) {
    unsigned int lo, hi;
    asm("mov.b64 {%0, %1}, %2;" : "=r"(lo), "=r"(hi) : "l"(v));
    return make_float2(__uint_as_float(lo), __uint_as_float(hi));
}

__device__ __forceinline__ float swishf(float a) {
    // a * sigmoid(a) = a / (1 + exp(-a))
    return a / (1.0f + __expf(-a));
}

// ---------------- kernel 0: init scratch ----------------
__global__ void k_init() {
    int i = blockIdx.x * blockDim.x + threadIdx.x;
    if (i < NE) { g_cnt[i] = 0; g_cur[i] = 0; }
    if (i < RCAP) g_rowtok[i] = -1;
}

// ---------------- kernel 1: gating (one warp per token) ----------------
__global__ void k_gate(const float* __restrict__ x, const float* __restrict__ Wg) {
    __shared__ float sWgT[NE * DIM];  // transposed [e][d], 32 KB
    for (int idx = threadIdx.x; idx < DIM * NE; idx += blockDim.x) {
        int d = idx >> 3, e = idx & 7;
        sWgT[e * DIM + d] = Wg[idx];
    }
    __syncthreads();

    int warp = threadIdx.x >> 5;
    int lane = threadIdx.x & 31;
    int t = blockIdx.x * (blockDim.x >> 5) + warp;
    if (t >= T_TOK) return;

    const float* xr = x + (size_t)t * DIM;
    float acc[NE];
#pragma unroll
    for (int e = 0; e < NE; e++) acc[e] = 0.0f;

    for (int d = lane; d < DIM; d += 32) {
        float xv = xr[d];
#pragma unroll
        for (int e = 0; e < NE; e++) acc[e] += xv * sWgT[e * DIM + d];
    }
#pragma unroll
    for (int off = 16; off; off >>= 1) {
#pragma unroll
        for (int e = 0; e < NE; e++)
            acc[e] += __shfl_xor_sync(0xffffffffu, acc[e], off);
    }
    if (lane == 0) {
        int e0 = 0; float v0 = acc[0];
#pragma unroll
        for (int e = 1; e < NE; e++) if (acc[e] > v0) { v0 = acc[e]; e0 = e; }
        int e1 = -1; float v1 = -1e30f;
#pragma unroll
        for (int e = 0; e < NE; e++) if (e != e0 && acc[e] > v1) { v1 = acc[e]; e1 = e; }
        float ex = __expf(v1 - v0);          // <= 1
        float p0 = 1.0f / (1.0f + ex);
        float p1 = ex / (1.0f + ex);
        g_tope[t * 2 + 0] = e0; g_topp[t * 2 + 0] = p0;
        g_tope[t * 2 + 1] = e1; g_topp[t * 2 + 1] = p1;
        atomicAdd(&g_cnt[e0], 1);
        atomicAdd(&g_cnt[e1], 1);
    }
}

// ---------------- kernel 2: padded exclusive scan of counts ----------------
__global__ void k_offsets() {
    if (threadIdx.x == 0) {
        int o = 0;
#pragma unroll
        for (int e = 0; e < NE; e++) {
            g_off[e] = o;
            o += ((g_cnt[e] + BM - 1) / BM) * BM;
        }
        g_off[NE] = o;
    }
}

// ---------------- kernel 3: scatter (token,k) -> row slot ----------------
__global__ void k_scatter() {
    int i = blockIdx.x * blockDim.x + threadIdx.x;
    if (i >= T_TOK * TOPK) return;
    int e = g_tope[i];
    int pos = g_off[e] + atomicAdd(&g_cur[e], 1);
    g_rowtok[pos] = i >> 1;
    g_roww[pos] = g_topp[i];
}

// ---------------- kernel 4: gather X rows (zero padding rows) ----------------
__global__ void k_gather(const float* __restrict__ x) {
    int r = blockIdx.x;
    int t = g_rowtok[r];
    float4* dst = (float4*)(g_X + (size_t)r * DIM);
    if (t >= 0) {
        const float4* src = (const float4*)(x + (size_t)t * DIM);
        for (int i = threadIdx.x; i < DIM / 4; i += blockDim.x) dst[i] = src[i];
    } else {
        for (int i = threadIdx.x; i < DIM / 4; i += blockDim.x)
            dst[i] = make_float4(0.f, 0.f, 0.f, 0.f);
    }
}

// ---------------- kernel 5: GEMM1  S = swish(X@W1) * (X@W2) ----------------
__global__ __launch_bounds__(256) void k_gemm1(const float* __restrict__ W1,
                                               const float* __restrict__ W2) {
    int row0 = blockIdx.y * BM;
    int e = 0;
#pragma unroll
    for (int i = 1; i < NE; i++) if (g_off[i] <= row0) e = i;
    int nvalid = g_cnt[e] - (row0 - g_off[e]);
    if (nvalid <= 0) return;

    const float* W1e = W1 + (size_t)e * DIM * HID;
    const float* W2e = W2 + (size_t)e * DIM * HID;
    int n0 = blockIdx.x * BN;

    __shared__ __align__(16) float As[BK][BM];
    __shared__ __align__(16) float B1s[BK][BN];
    __shared__ __align__(16) float B2s[BK][BN];

    int tid = threadIdx.x;
    int tx = tid & 15, ty = tid >> 4;
    int arow = tid >> 2, aseg = (tid & 3) * 4;
    int brow = tid >> 4, bseg = (tid & 15) * 4;

    unsigned long long acc1[4][2], acc2[4][2];
#pragma unroll
    for (int i = 0; i < 4; i++) { acc1[i][0]=acc1[i][1]=0ULL; acc2[i][0]=acc2[i][1]=0ULL; }

    const float* Xrow = g_X + (size_t)(row0 + arow) * DIM + aseg;

    float4 av = *(const float4*)(Xrow);
    float4 b1 = *(const float4*)(W1e + (size_t)brow * HID + n0 + bseg);
    float4 b2 = *(const float4*)(W2e + (size_t)brow * HID + n0 + bseg);

    for (int k0 = 0; k0 < DIM; k0 += BK) {
        __syncthreads();
        As[aseg + 0][arow] = av.x; As[aseg + 1][arow] = av.y;
        As[aseg + 2][arow] = av.z; As[aseg + 3][arow] = av.w;
        *(float4*)&B1s[brow][bseg] = b1;
        *(float4*)&B2s[brow][bseg] = b2;
        __syncthreads();

        int k1 = k0 + BK;
        if (k1 < DIM) {
            av = *(const float4*)(Xrow + k1);
            b1 = *(const float4*)(W1e + (size_t)(k1 + brow) * HID + n0 + bseg);
            b2 = *(const float4*)(W2e + (size_t)(k1 + brow) * HID + n0 + bseg);
        }
#pragma unroll
        for (int kk = 0; kk < BK; kk++) {
            float4 a = *(const float4*)&As[kk][ty * 4];
            ulonglong2 pb1 = *(const ulonglong2*)&B1s[kk][tx * 4];
            ulonglong2 pb2 = *(const ulonglong2*)&B2s[kk][tx * 4];
            unsigned long long ap0 = pack2(a.x), ap1 = pack2(a.y);
            unsigned long long ap2 = pack2(a.z), ap3 = pack2(a.w);
            acc1[0][0] = fma2(ap0, pb1.x, acc1[0][0]); acc1[0][1] = fma2(ap0, pb1.y, acc1[0][1]);
            acc1[1][0] = fma2(ap1, pb1.x, acc1[1][0]); acc1[1][1] = fma2(ap1, pb1.y, acc1[1][1]);
            acc1[2][0] = fma2(ap2, pb1.x, acc1[2][0]); acc1[2][1] = fma2(ap2, pb1.y, acc1[2][1]);
            acc1[3][0] = fma2(ap3, pb1.x, acc1[3][0]); acc1[3][1] = fma2(ap3, pb1.y, acc1[3][1]);
            acc2[0][0] = fma2(ap0, pb2.x, acc2[0][0]); acc2[0][1] = fma2(ap0, pb2.y, acc2[0][1]);
            acc2[1][0] = fma2(ap1, pb2.x, acc2[1][0]); acc2[1][1] = fma2(ap1, pb2.y, acc2[1][1]);
            acc2[2][0] = fma2(ap2, pb2.x, acc2[2][0]); acc2[2][1] = fma2(ap2, pb2.y, acc2[2][1]);
            acc2[3][0] = fma2(ap3, pb2.x, acc2[3][0]); acc2[3][1] = fma2(ap3, pb2.y, acc2[3][1]);
        }
    }

#pragma unroll
    for (int i = 0; i < 4; i++) {
        int r = ty * 4 + i;
        float2 a01 = unpack2(acc1[i][0]), a23 = unpack2(acc1[i][1]);
        float2 v01 = unpack2(acc2[i][0]), v23 = unpack2(acc2[i][1]);
        float4 o;
        o.x = swishf(a01.x) * v01.x;
        o.y = swishf(a01.y) * v01.y;
        o.z = swishf(a23.x) * v23.x;
        o.w = swishf(a23.y) * v23.y;
        *(float4*)(g_S + (size_t)(row0 + r) * HID + n0 + tx * 4) = o;
    }
}

// ---------------- kernel 6: GEMM2  out[t] += w * (S @ W3) ----------------
__global__ __launch_bounds__(256) void k_gemm2(const float* __restrict__ W3,
                                               float* __restrict__ out) {
    int row0 = blockIdx.y * BM;
    int e = 0;
#pragma unroll
    for (int i = 1; i < NE; i++) if (g_off[i] <= row0) e = i;
    int nvalid = g_cnt[e] - (row0 - g_off[e]);
    if (nvalid <= 0) return;

    const float* W3e = W3 + (size_t)e * HID * DIM;
    int n0 = blockIdx.x * BN;

    __shared__ __align__(16) float As[BK][BM];
    __shared__ __align__(16) float Bs[BK][BN];

    int tid = threadIdx.x;
    int tx = tid & 15, ty = tid >> 4;
    int arow = tid >> 2, aseg = (tid & 3) * 4;
    int brow = tid >> 4, bseg = (tid & 15) * 4;

    unsigned long long acc[4][2];
#pragma unroll
    for (int i = 0; i < 4; i++) { acc[i][0] = 0ULL; acc[i][1] = 0ULL; }

    const float* Srow = g_S + (size_t)(row0 + arow) * HID + aseg;

    float4 av = *(const float4*)(Srow);
    float4 bv = *(const float4*)(W3e + (size_t)brow * DIM + n0 + bseg);

    for (int k0 = 0; k0 < HID; k0 += BK) {
        __syncthreads();
        As[aseg + 0][arow] = av.x; As[aseg + 1][arow] = av.y;
        As[aseg + 2][arow] = av.z; As[aseg + 3][arow] = av.w;
        *(float4*)&Bs[brow][bseg] = bv;
        __syncthreads();

        int k1 = k0 + BK;
        if (k1 < HID) {
            av = *(const float4*)(Srow + k1);
            bv = *(const float4*)(W3e + (size_t)(k1 + brow) * DIM + n0 + bseg);
        }
#pragma unroll
        for (int kk = 0; kk < BK; kk++) {
            float4 a = *(const float4*)&As[kk][ty * 4];
            ulonglong2 pb = *(const ulonglong2*)&Bs[kk][tx * 4];
            unsigned long long ap0 = pack2(a.x), ap1 = pack2(a.y);
            unsigned long long ap2 = pack2(a.z), ap3 = pack2(a.w);
            acc[0][0] = fma2(ap0, pb.x, acc[0][0]); acc[0][1] = fma2(ap0, pb.y, acc[0][1]);
            acc[1][0] = fma2(ap1, pb.x, acc[1][0]); acc[1][1] = fma2(ap1, pb.y, acc[1][1]);
            acc[2][0] = fma2(ap2, pb.x, acc[2][0]); acc[2][1] = fma2(ap2, pb.y, acc[2][1]);
            acc[3][0] = fma2(ap3, pb.x, acc[3][0]); acc[3][1] = fma2(ap3, pb.y, acc[3][1]);
        }
    }

    int rowsvalid = nvalid < BM ? nvalid : BM;
#pragma unroll
    for (int i = 0; i < 4; i++) {
        int r = ty * 4 + i;
        if (r < rowsvalid) {
            int row = row0 + r;
            int t = g_rowtok[row];
            float w = g_roww[row];
            float2 y01 = unpack2(acc[i][0]), y23 = unpack2(acc[i][1]);
            float* orow = out + (size_t)t * DIM + n0 + tx * 4;
            atomicAdd(orow + 0, w * y01.x);
            atomicAdd(orow + 1, w * y01.y);
            atomicAdd(orow + 2, w * y23.x);
            atomicAdd(orow + 3, w * y23.y);
        }
    }
}

// ---------------- launch ----------------
extern "C" void kernel_launch(void* const* d_in, const int* in_sizes, int n_in,
                              void* d_out, int out_size) {
    const float* x  = (const float*)d_in[0];
    const float* Wg = (const float*)d_in[1];
    const float* W1 = (const float*)d_in[2];
    const float* W2 = (const float*)d_in[3];
    const float* W3 = (const float*)d_in[4];
    float* out = (float*)d_out;

    cudaMemsetAsync(out, 0, (size_t)T_TOK * DIM * sizeof(float));
    k_init<<<(RCAP + 255) / 256, 256>>>();
    k_gate<<<T_TOK / 8, 256>>>(x, Wg);
    k_offsets<<<1, 32>>>();
    k_scatter<<<(T_TOK * TOPK + 255) / 256, 256>>>();
    k_gather<<<RCAP, 256>>>(x);

    dim3 g1(HID / BN, RCAP / BM);
    k_gemm1<<<g1, 256>>>(W1, W2);
    dim3 g2(DIM / BN, RCAP / BM);
    k_gemm2<<<g2, 256>>>(W3, out);
}

// round 3
// speedup vs baseline: 2.1567x; 2.1567x over previous
#include <cuda_runtime.h>
#include <cuda_bf16.h>
#include <cstdint>

#define T_TOK 8192
#define DIM   1024
#define HID   2048
#define NE    8
#define BM    128
#define BN    128
#define BK    32
#define RCAP  (T_TOK*2 + NE*BM)   // 17408 rows = 136 tiles of 128

// smem tile geometry: 128 rows x 32 bf16 (64B) padded to 80B rows
#define ROWB   80
#define TILEB  (128*ROWB)          // 10240 B
#define STAGEB (4*TILEB)           // Ah, Al, Bh, Bl = 40960 B
#define NSTAGE 3
#define SMEMSZ (NSTAGE*STAGEB)     // 122880 B

// ---------------- device scratch ----------------
__device__ int   g_cnt[NE], g_cur[NE], g_off[NE + 1];
__device__ int   g_tope[T_TOK * 2];
__device__ float g_topp[T_TOK * 2];
__device__ int   g_rowtok[RCAP];
__device__ float g_roww[RCAP];
__device__ __nv_bfloat16 g_Xh[(size_t)RCAP * DIM];
__device__ __nv_bfloat16 g_Xl[(size_t)RCAP * DIM];
__device__ __nv_bfloat16 g_Sh[(size_t)RCAP * HID];
__device__ __nv_bfloat16 g_Sl[(size_t)RCAP * HID];
__device__ __nv_bfloat16 g_Wch[(size_t)NE * 2 * HID * DIM];  // [e][2h+p][d]
__device__ __nv_bfloat16 g_Wcl[(size_t)NE * 2 * HID * DIM];
__device__ __nv_bfloat16 g_W3h[(size_t)NE * DIM * HID];      // [e][d][h]
__device__ __nv_bfloat16 g_W3l[(size_t)NE * DIM * HID];

// ---------------- helpers ----------------
__device__ __forceinline__ uint32_t smem_u32(const void* p) {
    uint32_t a;
    asm("{ .reg .u64 t; cvta.to.shared.u64 t, %1; cvt.u32.u64 %0, t; }" : "=r"(a) : "l"(p));
    return a;
}
__device__ __forceinline__ void cp16(uint32_t dst, const void* src) {
    asm volatile("cp.async.cg.shared.global [%0], [%1], 16;" :: "r"(dst), "l"(src));
}
#define CP_COMMIT() asm volatile("cp.async.commit_group;" ::: "memory")
#define CP_WAIT1()  asm volatile("cp.async.wait_group 1;" ::: "memory")

__device__ __forceinline__ void ldsm4(uint32_t* r, uint32_t addr) {
    asm volatile("ldmatrix.sync.aligned.m8n8.x4.shared.b16 {%0,%1,%2,%3}, [%4];"
                 : "=r"(r[0]), "=r"(r[1]), "=r"(r[2]), "=r"(r[3]) : "r"(addr));
}
__device__ __forceinline__ void mma_bf16(float* c, const uint32_t* a, uint32_t b0, uint32_t b1) {
    asm volatile("mma.sync.aligned.m16n8k16.row.col.f32.bf16.bf16.f32 "
                 "{%0,%1,%2,%3}, {%4,%5,%6,%7}, {%8,%9}, {%0,%1,%2,%3};"
                 : "+f"(c[0]), "+f"(c[1]), "+f"(c[2]), "+f"(c[3])
                 : "r"(a[0]), "r"(a[1]), "r"(a[2]), "r"(a[3]), "r"(b0), "r"(b1));
}
__device__ __forceinline__ float swishf(float a) { return a / (1.0f + __expf(-a)); }
__device__ __forceinline__ void bsplit(float v, __nv_bfloat16& h, __nv_bfloat16& l) {
    h = __float2bfloat16(v);
    l = __float2bfloat16(v - __bfloat162float(h));
}

// ---------------- routing kernels ----------------
__global__ void k_init() {
    int i = blockIdx.x * blockDim.x + threadIdx.x;
    if (i < NE) { g_cnt[i] = 0; g_cur[i] = 0; }
    if (i < RCAP) g_rowtok[i] = -1;
}

__global__ void k_gate(const float* __restrict__ x, const float* __restrict__ Wg) {
    __shared__ float sWgT[NE * DIM];
    for (int idx = threadIdx.x; idx < DIM * NE; idx += blockDim.x) {
        int d = idx >> 3, e = idx & 7;
        sWgT[e * DIM + d] = Wg[idx];
    }
    __syncthreads();
    int warp = threadIdx.x >> 5, lane = threadIdx.x & 31;
    int t = blockIdx.x * 8 + warp;
    const float* xr = x + (size_t)t * DIM;
    float acc[NE];
#pragma unroll
    for (int e = 0; e < NE; e++) acc[e] = 0.0f;
    for (int d = lane; d < DIM; d += 32) {
        float xv = xr[d];
#pragma unroll
        for (int e = 0; e < NE; e++) acc[e] += xv * sWgT[e * DIM + d];
    }
#pragma unroll
    for (int off = 16; off; off >>= 1)
#pragma unroll
        for (int e = 0; e < NE; e++) acc[e] += __shfl_xor_sync(0xffffffffu, acc[e], off);
    if (lane == 0) {
        int e0 = 0; float v0 = acc[0];
#pragma unroll
        for (int e = 1; e < NE; e++) if (acc[e] > v0) { v0 = acc[e]; e0 = e; }
        int e1 = -1; float v1 = -1e30f;
#pragma unroll
        for (int e = 0; e < NE; e++) if (e != e0 && acc[e] > v1) { v1 = acc[e]; e1 = e; }
        float ex = __expf(v1 - v0);
        g_tope[t * 2 + 0] = e0; g_topp[t * 2 + 0] = 1.0f / (1.0f + ex);
        g_tope[t * 2 + 1] = e1; g_topp[t * 2 + 1] = ex / (1.0f + ex);
        atomicAdd(&g_cnt[e0], 1);
        atomicAdd(&g_cnt[e1], 1);
    }
}

__global__ void k_offsets() {
    if (threadIdx.x == 0) {
        int o = 0;
#pragma unroll
        for (int e = 0; e < NE; e++) {
            g_off[e] = o;
            o += ((g_cnt[e] + BM - 1) / BM) * BM;
        }
        g_off[NE] = o;
    }
}

__global__ void k_scatter() {
    int i = blockIdx.x * blockDim.x + threadIdx.x;
    if (i >= T_TOK * 2) return;
    int e = g_tope[i];
    int pos = g_off[e] + atomicAdd(&g_cur[e], 1);
    g_rowtok[pos] = i >> 1;
    g_roww[pos] = g_topp[i];
}

// gather + bf16 split of X rows
__global__ void k_gather(const float* __restrict__ x) {
    int r = blockIdx.x;
    int t = g_rowtok[r];
    int i = threadIdx.x;              // 256 threads, 4 floats each
    float4 v = make_float4(0.f, 0.f, 0.f, 0.f);
    if (t >= 0) v = ((const float4*)(x + (size_t)t * DIM))[i];
    __nv_bfloat16 h[4], l[4];
    bsplit(v.x, h[0], l[0]); bsplit(v.y, h[1], l[1]);
    bsplit(v.z, h[2], l[2]); bsplit(v.w, h[3], l[3]);
    size_t off = (size_t)r * DIM + i * 4;
    *(ushort4*)(g_Xh + off) = make_ushort4(*(unsigned short*)&h[0], *(unsigned short*)&h[1],
                                           *(unsigned short*)&h[2], *(unsigned short*)&h[3]);
    *(ushort4*)(g_Xl + off) = make_ushort4(*(unsigned short*)&l[0], *(unsigned short*)&l[1],
                                           *(unsigned short*)&l[2], *(unsigned short*)&l[3]);
}

// W1/W2 [e][d][h] -> Wc [e][2h+p][d] (bf16 h/l), interleaved columns
__global__ void k_tr12(const float* __restrict__ src, int p) {
    __shared__ float t[32][33];
    int e = blockIdx.z;
    const float* s = src + (size_t)e * DIM * HID;
    int h0 = blockIdx.x * 32, d0 = blockIdx.y * 32;
    int tx = threadIdx.x, ty = threadIdx.y;
#pragma unroll
    for (int i = ty; i < 32; i += 8)
        t[i][tx] = s[(size_t)(d0 + i) * HID + h0 + tx];
    __syncthreads();
#pragma unroll
    for (int i = ty; i < 32; i += 8) {
        float v = t[tx][i];           // = s[d0+tx][h0+i]
        int n = 2 * (h0 + i) + p;
        __nv_bfloat16 h, l; bsplit(v, h, l);
        size_t off = ((size_t)e * 2 * HID + n) * DIM + d0 + tx;
        g_Wch[off] = h; g_Wcl[off] = l;
    }
}

// W3 [e][h][d] -> W3T [e][d][h] (bf16 h/l)
__global__ void k_tr3(const float* __restrict__ src) {
    __shared__ float t[32][33];
    int e = blockIdx.z;
    const float* s = src + (size_t)e * HID * DIM;
    int d0 = blockIdx.x * 32, h0 = blockIdx.y * 32;
    int tx = threadIdx.x, ty = threadIdx.y;
#pragma unroll
    for (int i = ty; i < 32; i += 8)
        t[i][tx] = s[(size_t)(h0 + i) * DIM + d0 + tx];
    __syncthreads();
#pragma unroll
    for (int i = ty; i < 32; i += 8) {
        float v = t[tx][i];           // = s[h0+tx][d0+i]
        __nv_bfloat16 h, l; bsplit(v, h, l);
        size_t off = ((size_t)e * DIM + d0 + i) * HID + h0 + tx;
        g_W3h[off] = h; g_W3l[off] = l;
    }
}

// ---------------- stage loader (shared by both GEMMs) ----------------
__device__ __forceinline__ void load_stage(
    uint32_t st, int tid, int k0, int kstride,
    const __nv_bfloat16* Ah, const __nv_bfloat16* Al,
    const __nv_bfloat16* Bh, const __nv_bfloat16* Bl)
{
#pragma unroll
    for (int rep = 0; rep < 2; rep++) {
        int c = tid + rep * 256;          // 0..511
        int row = c >> 2, kc = c & 3;
        uint32_t doff = row * ROWB + kc * 16;
        size_t goff = (size_t)row * kstride + k0 + kc * 8;
        cp16(st + doff,             Ah + goff);
        cp16(st + TILEB + doff,     Al + goff);
        cp16(st + 2 * TILEB + doff, Bh + goff);
        cp16(st + 3 * TILEB + doff, Bl + goff);
    }
    CP_COMMIT();
}

// compute one BK=32 stage: 2 k16 steps, bf16x3
__device__ __forceinline__ void compute_stage(
    uint32_t st, int warpM, int warpN, int lane, float acc[2][8][4])
{
    int mlane = lane & 7;
    int mid = lane >> 3;                  // matrix id 0..3
#pragma unroll
    for (int ks = 0; ks < 2; ks++) {
        uint32_t ah[2][4], al[2][4], bh[4][4], bl[4][4];
#pragma unroll
        for (int mi = 0; mi < 2; mi++) {
            int row = warpM * 32 + mi * 16 + ((mid & 1) << 3) + mlane;
            int colB = ks * 32 + ((mid >> 1) << 4);
            ldsm4(ah[mi], st + row * ROWB + colB);
            ldsm4(al[mi], st + TILEB + row * ROWB + colB);
        }
#pragma unroll
        for (int nj = 0; nj < 4; nj++) {
            int row = warpN * 64 + nj * 16 + ((mid >> 1) << 3) + mlane;
            int colB = ks * 32 + ((mid & 1) << 4);
            ldsm4(bh[nj], st + 2 * TILEB + row * ROWB + colB);
            ldsm4(bl[nj], st + 3 * TILEB + row * ROWB + colB);
        }
#pragma unroll
        for (int mi = 0; mi < 2; mi++)
#pragma unroll
            for (int nj = 0; nj < 4; nj++)
#pragma unroll
                for (int tt = 0; tt < 2; tt++) {
                    int ni = nj * 2 + tt;
                    mma_bf16(acc[mi][ni], ah[mi], bh[nj][tt * 2], bh[nj][tt * 2 + 1]);
                    mma_bf16(acc[mi][ni], ah[mi], bl[nj][tt * 2], bl[nj][tt * 2 + 1]);
                    mma_bf16(acc[mi][ni], al[mi], bh[nj][tt * 2], bh[nj][tt * 2 + 1]);
                }
    }
}

// ---------------- GEMM1: [RCAP,4096] = X @ Wc, epilogue SwiGLU -> Sh/Sl ----------------
__global__ __launch_bounds__(256) void k_gemm1() {
    int row0 = blockIdx.y * BM;
    int e = 0;
#pragma unroll
    for (int i = 1; i < NE; i++) if (g_off[i] <= row0) e = i;
    if (g_cnt[e] - (row0 - g_off[e]) <= 0) return;

    extern __shared__ __align__(128) char smem[];
    uint32_t sb = smem_u32(smem);
    int tid = threadIdx.x, wid = tid >> 5, lane = tid & 31;
    int warpM = wid >> 1, warpN = wid & 1;
    int n0 = blockIdx.x * BN;

    const __nv_bfloat16* Ah = g_Xh + (size_t)row0 * DIM;
    const __nv_bfloat16* Al = g_Xl + (size_t)row0 * DIM;
    const __nv_bfloat16* Bh = g_Wch + (size_t)e * 2 * HID * DIM + (size_t)n0 * DIM;
    const __nv_bfloat16* Bl = g_Wcl + (size_t)e * 2 * HID * DIM + (size_t)n0 * DIM;

    float acc[2][8][4];
#pragma unroll
    for (int a = 0; a < 2; a++)
#pragma unroll
        for (int b = 0; b < 8; b++)
#pragma unroll
            for (int c = 0; c < 4; c++) acc[a][b][c] = 0.0f;

    const int NC = DIM / BK;   // 32
    load_stage(sb, tid, 0, DIM, Ah, Al, Bh, Bl);
    load_stage(sb + STAGEB, tid, BK, DIM, Ah, Al, Bh, Bl);

    for (int c = 0; c < NC; c++) {
        CP_WAIT1();
        __syncthreads();
        if (c + 2 < NC)
            load_stage(sb + ((c + 2) % NSTAGE) * STAGEB, tid, (c + 2) * BK, DIM, Ah, Al, Bh, Bl);
        compute_stage(sb + (c % NSTAGE) * STAGEB, warpM, warpN, lane, acc);
    }

    // epilogue: pairs (c0,c1)/(c2,c3) = (a1,a2) per hidden unit -> swish(a1)*a2
    int qrow = lane >> 2, qcol = lane & 3;
#pragma unroll
    for (int mi = 0; mi < 2; mi++) {
#pragma unroll
        for (int ni = 0; ni < 8; ni++) {
            int jg = blockIdx.x * 64 + warpN * 32 + ni * 4 + qcol;
            int r = row0 + warpM * 32 + mi * 16 + qrow;
            float v0 = swishf(acc[mi][ni][0]) * acc[mi][ni][1];
            float v1 = swishf(acc[mi][ni][2]) * acc[mi][ni][3];
            __nv_bfloat16 h, l;
            bsplit(v0, h, l);
            g_Sh[(size_t)r * HID + jg] = h;       g_Sl[(size_t)r * HID + jg] = l;
            bsplit(v1, h, l);
            g_Sh[(size_t)(r + 8) * HID + jg] = h; g_Sl[(size_t)(r + 8) * HID + jg] = l;
        }
    }
}

// ---------------- GEMM2: out[t] += w * (S @ W3T) ----------------
__global__ __launch_bounds__(256) void k_gemm2(float* __restrict__ out) {
    int row0 = blockIdx.y * BM;
    int e = 0;
#pragma unroll
    for (int i = 1; i < NE; i++) if (g_off[i] <= row0) e = i;
    if (g_cnt[e] - (row0 - g_off[e]) <= 0) return;

    extern __shared__ __align__(128) char smem[];
    uint32_t sb = smem_u32(smem);
    int tid = threadIdx.x, wid = tid >> 5, lane = tid & 31;
    int warpM = wid >> 1, warpN = wid & 1;
    int n0 = blockIdx.x * BN;

    const __nv_bfloat16* Ah = g_Sh + (size_t)row0 * HID;
    const __nv_bfloat16* Al = g_Sl + (size_t)row0 * HID;
    const __nv_bfloat16* Bh = g_W3h + (size_t)e * DIM * HID + (size_t)n0 * HID;
    const __nv_bfloat16* Bl = g_W3l + (size_t)e * DIM * HID + (size_t)n0 * HID;

    float acc[2][8][4];
#pragma unroll
    for (int a = 0; a < 2; a++)
#pragma unroll
        for (int b = 0; b < 8; b++)
#pragma unroll
            for (int c = 0; c < 4; c++) acc[a][b][c] = 0.0f;

    const int NC = HID / BK;   // 64
    load_stage(sb, tid, 0, HID, Ah, Al, Bh, Bl);
    load_stage(sb + STAGEB, tid, BK, HID, Ah, Al, Bh, Bl);

    for (int c = 0; c < NC; c++) {
        CP_WAIT1();
        __syncthreads();
        if (c + 2 < NC)
            load_stage(sb + ((c + 2) % NSTAGE) * STAGEB, tid, (c + 2) * BK, HID, Ah, Al, Bh, Bl);
        compute_stage(sb + (c % NSTAGE) * STAGEB, warpM, warpN, lane, acc);
    }

    int qrow = lane >> 2, qcol = lane & 3;
#pragma unroll
    for (int mi = 0; mi < 2; mi++) {
        int rbase = row0 + warpM * 32 + mi * 16 + qrow;
#pragma unroll
        for (int half = 0; half < 2; half++) {
            int r = rbase + half * 8;
            int t = g_rowtok[r];
            if (t < 0) continue;
            float wgt = g_roww[r];
            float* orow = out + (size_t)t * DIM;
#pragma unroll
            for (int ni = 0; ni < 8; ni++) {
                int colg = blockIdx.x * BN + warpN * 64 + ni * 8 + qcol * 2;
                atomicAdd(orow + colg,     wgt * acc[mi][ni][half * 2]);
                atomicAdd(orow + colg + 1, wgt * acc[mi][ni][half * 2 + 1]);
            }
        }
    }
}

// ---------------- launch ----------------
extern "C" void kernel_launch(void* const* d_in, const int* in_sizes, int n_in,
                              void* d_out, int out_size) {
    const float* x  = (const float*)d_in[0];
    const float* Wg = (const float*)d_in[1];
    const float* W1 = (const float*)d_in[2];
    const float* W2 = (const float*)d_in[3];
    const float* W3 = (const float*)d_in[4];
    float* out = (float*)d_out;

    cudaFuncSetAttribute(k_gemm1, cudaFuncAttributeMaxDynamicSharedMemorySize, SMEMSZ);
    cudaFuncSetAttribute(k_gemm2, cudaFuncAttributeMaxDynamicSharedMemorySize, SMEMSZ);

    cudaMemsetAsync(out, 0, (size_t)T_TOK * DIM * sizeof(float));
    k_init<<<(RCAP + 255) / 256, 256>>>();
    k_gate<<<T_TOK / 8, 256>>>(x, Wg);
    k_offsets<<<1, 32>>>();
    k_scatter<<<(T_TOK * 2 + 255) / 256, 256>>>();
    k_gather<<<RCAP, 256>>>(x);
    k_tr12<<<dim3(HID / 32, DIM / 32, NE), dim3(32, 8)>>>(W1, 0);
    k_tr12<<<dim3(HID / 32, DIM / 32, NE), dim3(32, 8)>>>(W2, 1);
    k_tr3<<<dim3(DIM / 32, HID / 32, NE), dim3(32, 8)>>>(W3);

    k_gemm1<<<dim3(2 * HID / BN, RCAP / BM), 256, SMEMSZ>>>();
    k_gemm2<<<dim3(DIM / BN, RCAP / BM), 256, SMEMSZ>>>(out);
}

// round 4
// speedup vs baseline: 2.5526x; 1.1835x over previous
#include <cuda_runtime.h>
#include <cuda_bf16.h>
#include <cstdint>

#define T_TOK 8192
#define DIM   1024
#define HID   2048
#define NE    8
#define BM    128
#define BN    128
#define BK    32
#define RCAP  (T_TOK*2 + NE*BM)   // 17408 rows = 136 tiles of 128

// smem tile: 128 rows x 32 bf16 (64B) padded to 80B rows (conflict-free ldmatrix)
#define ROWB   80
#define TILEB  (128*ROWB)          // 10240 B
#define STAGEB (4*TILEB)           // Ah, Al, Bh, Bl = 40960 B
#define NSTAGE 2
#define SMEMSZ (NSTAGE*STAGEB)     // 81920 B -> 2 CTAs/SM

// ---------------- device scratch ----------------
__device__ int   g_cnt[NE], g_cur[NE], g_off[NE + 1];
__device__ int   g_tope[T_TOK * 2];
__device__ float g_topp[T_TOK * 2];
__device__ int   g_rowtok[RCAP];
__device__ float g_roww[RCAP];
__device__ __nv_bfloat16 g_Xh[(size_t)RCAP * DIM];
__device__ __nv_bfloat16 g_Xl[(size_t)RCAP * DIM];
__device__ __nv_bfloat16 g_Sh[(size_t)RCAP * HID];
__device__ __nv_bfloat16 g_Sl[(size_t)RCAP * HID];
__device__ __nv_bfloat16 g_Wch[(size_t)NE * 2 * HID * DIM];  // [e][2h+p][d]
__device__ __nv_bfloat16 g_Wcl[(size_t)NE * 2 * HID * DIM];
__device__ __nv_bfloat16 g_W3h[(size_t)NE * DIM * HID];      // [e][d][h]
__device__ __nv_bfloat16 g_W3l[(size_t)NE * DIM * HID];

// ---------------- helpers ----------------
__device__ __forceinline__ uint32_t smem_u32(const void* p) {
    uint32_t a;
    asm("{ .reg .u64 t; cvta.to.shared.u64 t, %1; cvt.u32.u64 %0, t; }" : "=r"(a) : "l"(p));
    return a;
}
__device__ __forceinline__ void cp16(uint32_t dst, const void* src) {
    asm volatile("cp.async.cg.shared.global [%0], [%1], 16;" :: "r"(dst), "l"(src));
}
#define CP_COMMIT() asm volatile("cp.async.commit_group;" ::: "memory")
#define CP_WAIT1()  asm volatile("cp.async.wait_group 1;" ::: "memory")
#define CP_WAIT0()  asm volatile("cp.async.wait_group 0;" ::: "memory")

__device__ __forceinline__ void ldsm4(uint32_t* r, uint32_t addr) {
    asm volatile("ldmatrix.sync.aligned.m8n8.x4.shared.b16 {%0,%1,%2,%3}, [%4];"
                 : "=r"(r[0]), "=r"(r[1]), "=r"(r[2]), "=r"(r[3]) : "r"(addr));
}
__device__ __forceinline__ void mma_bf16(float* c, const uint32_t* a, uint32_t b0, uint32_t b1) {
    asm volatile("mma.sync.aligned.m16n8k16.row.col.f32.bf16.bf16.f32 "
                 "{%0,%1,%2,%3}, {%4,%5,%6,%7}, {%8,%9}, {%0,%1,%2,%3};"
                 : "+f"(c[0]), "+f"(c[1]), "+f"(c[2]), "+f"(c[3])
                 : "r"(a[0]), "r"(a[1]), "r"(a[2]), "r"(a[3]), "r"(b0), "r"(b1));
}
__device__ __forceinline__ float swishf(float a) { return a / (1.0f + __expf(-a)); }
__device__ __forceinline__ void bsplit(float v, __nv_bfloat16& h, __nv_bfloat16& l) {
    h = __float2bfloat16(v);
    l = __float2bfloat16(v - __bfloat162float(h));
}

// ---------------- routing kernels ----------------
__global__ void k_init() {
    int i = blockIdx.x * blockDim.x + threadIdx.x;
    if (i < NE) { g_cnt[i] = 0; g_cur[i] = 0; }
    if (i < RCAP) g_rowtok[i] = -1;
}

__global__ void k_gate(const float* __restrict__ x, const float* __restrict__ Wg) {
    __shared__ float sWgT[NE * DIM];
    for (int idx = threadIdx.x; idx < DIM * NE; idx += blockDim.x) {
        int d = idx >> 3, e = idx & 7;
        sWgT[e * DIM + d] = Wg[idx];
    }
    __syncthreads();
    int warp = threadIdx.x >> 5, lane = threadIdx.x & 31;
    int t = blockIdx.x * 8 + warp;
    const float* xr = x + (size_t)t * DIM;
    float acc[NE];
#pragma unroll
    for (int e = 0; e < NE; e++) acc[e] = 0.0f;
    for (int d = lane; d < DIM; d += 32) {
        float xv = xr[d];
#pragma unroll
        for (int e = 0; e < NE; e++) acc[e] += xv * sWgT[e * DIM + d];
    }
#pragma unroll
    for (int off = 16; off; off >>= 1)
#pragma unroll
        for (int e = 0; e < NE; e++) acc[e] += __shfl_xor_sync(0xffffffffu, acc[e], off);
    if (lane == 0) {
        int e0 = 0; float v0 = acc[0];
#pragma unroll
        for (int e = 1; e < NE; e++) if (acc[e] > v0) { v0 = acc[e]; e0 = e; }
        int e1 = -1; float v1 = -1e30f;
#pragma unroll
        for (int e = 0; e < NE; e++) if (e != e0 && acc[e] > v1) { v1 = acc[e]; e1 = e; }
        float ex = __expf(v1 - v0);
        g_tope[t * 2 + 0] = e0; g_topp[t * 2 + 0] = 1.0f / (1.0f + ex);
        g_tope[t * 2 + 1] = e1; g_topp[t * 2 + 1] = ex / (1.0f + ex);
        atomicAdd(&g_cnt[e0], 1);
        atomicAdd(&g_cnt[e1], 1);
    }
}

__global__ void k_offsets() {
    if (threadIdx.x == 0) {
        int o = 0;
#pragma unroll
        for (int e = 0; e < NE; e++) {
            g_off[e] = o;
            o += ((g_cnt[e] + BM - 1) / BM) * BM;
        }
        g_off[NE] = o;
    }
}

__global__ void k_scatter() {
    int i = blockIdx.x * blockDim.x + threadIdx.x;
    if (i >= T_TOK * 2) return;
    int e = g_tope[i];
    int pos = g_off[e] + atomicAdd(&g_cur[e], 1);
    g_rowtok[pos] = i >> 1;
    g_roww[pos] = g_topp[i];
}

__global__ void k_gather(const float* __restrict__ x) {
    int r = blockIdx.x;
    int t = g_rowtok[r];
    int i = threadIdx.x;
    float4 v = make_float4(0.f, 0.f, 0.f, 0.f);
    if (t >= 0) v = ((const float4*)(x + (size_t)t * DIM))[i];
    __nv_bfloat16 h[4], l[4];
    bsplit(v.x, h[0], l[0]); bsplit(v.y, h[1], l[1]);
    bsplit(v.z, h[2], l[2]); bsplit(v.w, h[3], l[3]);
    size_t off = (size_t)r * DIM + i * 4;
    *(ushort4*)(g_Xh + off) = make_ushort4(*(unsigned short*)&h[0], *(unsigned short*)&h[1],
                                           *(unsigned short*)&h[2], *(unsigned short*)&h[3]);
    *(ushort4*)(g_Xl + off) = make_ushort4(*(unsigned short*)&l[0], *(unsigned short*)&l[1],
                                           *(unsigned short*)&l[2], *(unsigned short*)&l[3]);
}

// W1/W2 [e][d][h] -> Wc [e][2h+p][d] (bf16 h/l), interleaved columns
__global__ void k_tr12(const float* __restrict__ src, int p) {
    __shared__ float t[32][33];
    int e = blockIdx.z;
    const float* s = src + (size_t)e * DIM * HID;
    int h0 = blockIdx.x * 32, d0 = blockIdx.y * 32;
    int tx = threadIdx.x, ty = threadIdx.y;
#pragma unroll
    for (int i = ty; i < 32; i += 8)
        t[i][tx] = s[(size_t)(d0 + i) * HID + h0 + tx];
    __syncthreads();
#pragma unroll
    for (int i = ty; i < 32; i += 8) {
        float v = t[tx][i];
        int n = 2 * (h0 + i) + p;
        __nv_bfloat16 h, l; bsplit(v, h, l);
        size_t off = ((size_t)e * 2 * HID + n) * DIM + d0 + tx;
        g_Wch[off] = h; g_Wcl[off] = l;
    }
}

// W3 [e][h][d] -> W3T [e][d][h] (bf16 h/l)
__global__ void k_tr3(const float* __restrict__ src) {
    __shared__ float t[32][33];
    int e = blockIdx.z;
    const float* s = src + (size_t)e * HID * DIM;
    int d0 = blockIdx.x * 32, h0 = blockIdx.y * 32;
    int tx = threadIdx.x, ty = threadIdx.y;
#pragma unroll
    for (int i = ty; i < 32; i += 8)
        t[i][tx] = s[(size_t)(h0 + i) * DIM + d0 + tx];
    __syncthreads();
#pragma unroll
    for (int i = ty; i < 32; i += 8) {
        float v = t[tx][i];
        __nv_bfloat16 h, l; bsplit(v, h, l);
        size_t off = ((size_t)e * DIM + d0 + i) * HID + h0 + tx;
        g_W3h[off] = h; g_W3l[off] = l;
    }
}

// ---------------- stage loader ----------------
__device__ __forceinline__ void load_stage(
    uint32_t st, int tid, int k0, int kstride,
    const __nv_bfloat16* Ah, const __nv_bfloat16* Al,
    const __nv_bfloat16* Bh, const __nv_bfloat16* Bl)
{
#pragma unroll
    for (int rep = 0; rep < 2; rep++) {
        int c = tid + rep * 256;
        int row = c >> 2, kc = c & 3;
        uint32_t doff = row * ROWB + kc * 16;
        size_t goff = (size_t)row * kstride + k0 + kc * 8;
        cp16(st + doff,             Ah + goff);
        cp16(st + TILEB + doff,     Al + goff);
        cp16(st + 2 * TILEB + doff, Bh + goff);
        cp16(st + 3 * TILEB + doff, Bl + goff);
    }
    CP_COMMIT();
}

// compute one BK=32 stage; B fragments loaded in two halves to cap live regs
__device__ __forceinline__ void compute_stage(
    uint32_t st, int warpM, int warpN, int lane, float acc[2][8][4])
{
    int mlane = lane & 7;
    int mid = lane >> 3;
#pragma unroll
    for (int ks = 0; ks < 2; ks++) {
        uint32_t ah[2][4], al[2][4];
#pragma unroll
        for (int mi = 0; mi < 2; mi++) {
            int row = warpM * 32 + mi * 16 + ((mid & 1) << 3) + mlane;
            int colB = ks * 32 + ((mid >> 1) << 4);
            ldsm4(ah[mi], st + row * ROWB + colB);
            ldsm4(al[mi], st + TILEB + row * ROWB + colB);
        }
#pragma unroll
        for (int njp = 0; njp < 2; njp++) {
            uint32_t bh[2][4], bl[2][4];
#pragma unroll
            for (int jj = 0; jj < 2; jj++) {
                int nj = njp * 2 + jj;
                int row = warpN * 64 + nj * 16 + ((mid >> 1) << 3) + mlane;
                int colB = ks * 32 + ((mid & 1) << 4);
                ldsm4(bh[jj], st + 2 * TILEB + row * ROWB + colB);
                ldsm4(bl[jj], st + 3 * TILEB + row * ROWB + colB);
            }
#pragma unroll
            for (int mi = 0; mi < 2; mi++)
#pragma unroll
                for (int jj = 0; jj < 2; jj++)
#pragma unroll
                    for (int tt = 0; tt < 2; tt++) {
                        int ni = (njp * 2 + jj) * 2 + tt;
                        mma_bf16(acc[mi][ni], ah[mi], bh[jj][tt * 2], bh[jj][tt * 2 + 1]);
                        mma_bf16(acc[mi][ni], ah[mi], bl[jj][tt * 2], bl[jj][tt * 2 + 1]);
                        mma_bf16(acc[mi][ni], al[mi], bh[jj][tt * 2], bh[jj][tt * 2 + 1]);
                    }
        }
    }
}

// ---------------- GEMM mainloop (shared pattern) ----------------
#define GEMM_MAINLOOP(NC, KSTRIDE)                                                  \
    load_stage(sb, tid, 0, KSTRIDE, Ah, Al, Bh, Bl);                                \
    load_stage(sb + STAGEB, tid, BK, KSTRIDE, Ah, Al, Bh, Bl);                      \
    for (int c = 0; c < (NC); c++) {                                                \
        if (c == (NC) - 1) { CP_WAIT0(); } else { CP_WAIT1(); }                     \
        __syncthreads();                                                            \
        compute_stage(sb + (c & 1) * STAGEB, warpM, warpN, lane, acc);              \
        __syncthreads();                                                            \
        if (c + 2 < (NC))                                                           \
            load_stage(sb + (c & 1) * STAGEB, tid, (c + 2) * BK, KSTRIDE,           \
                       Ah, Al, Bh, Bl);                                             \
    }

// ---------------- GEMM1: [RCAP,4096] = X @ Wc, epilogue SwiGLU -> Sh/Sl ----------------
__global__ __launch_bounds__(256, 2) void k_gemm1() {
    int row0 = blockIdx.y * BM;
    int e = 0;
#pragma unroll
    for (int i = 1; i < NE; i++) if (g_off[i] <= row0) e = i;
    if (g_cnt[e] - (row0 - g_off[e]) <= 0) return;

    extern __shared__ __align__(128) char smem[];
    uint32_t sb = smem_u32(smem);
    int tid = threadIdx.x, wid = tid >> 5, lane = tid & 31;
    int warpM = wid >> 1, warpN = wid & 1;
    int n0 = blockIdx.x * BN;

    const __nv_bfloat16* Ah = g_Xh + (size_t)row0 * DIM;
    const __nv_bfloat16* Al = g_Xl + (size_t)row0 * DIM;
    const __nv_bfloat16* Bh = g_Wch + (size_t)e * 2 * HID * DIM + (size_t)n0 * DIM;
    const __nv_bfloat16* Bl = g_Wcl + (size_t)e * 2 * HID * DIM + (size_t)n0 * DIM;

    float acc[2][8][4];
#pragma unroll
    for (int a = 0; a < 2; a++)
#pragma unroll
        for (int b = 0; b < 8; b++)
#pragma unroll
            for (int c = 0; c < 4; c++) acc[a][b][c] = 0.0f;

    GEMM_MAINLOOP(DIM / BK, DIM)

    int qrow = lane >> 2, qcol = lane & 3;
#pragma unroll
    for (int mi = 0; mi < 2; mi++) {
#pragma unroll
        for (int ni = 0; ni < 8; ni++) {
            int jg = blockIdx.x * 64 + warpN * 32 + ni * 4 + qcol;
            int r = row0 + warpM * 32 + mi * 16 + qrow;
            float v0 = swishf(acc[mi][ni][0]) * acc[mi][ni][1];
            float v1 = swishf(acc[mi][ni][2]) * acc[mi][ni][3];
            __nv_bfloat16 h, l;
            bsplit(v0, h, l);
            g_Sh[(size_t)r * HID + jg] = h;       g_Sl[(size_t)r * HID + jg] = l;
            bsplit(v1, h, l);
            g_Sh[(size_t)(r + 8) * HID + jg] = h; g_Sl[(size_t)(r + 8) * HID + jg] = l;
        }
    }
}

// ---------------- GEMM2: out[t] += w * (S @ W3T) ----------------
__global__ __launch_bounds__(256, 2) void k_gemm2(float* __restrict__ out) {
    int row0 = blockIdx.y * BM;
    int e = 0;
#pragma unroll
    for (int i = 1; i < NE; i++) if (g_off[i] <= row0) e = i;
    if (g_cnt[e] - (row0 - g_off[e]) <= 0) return;

    extern __shared__ __align__(128) char smem[];
    uint32_t sb = smem_u32(smem);
    int tid = threadIdx.x, wid = tid >> 5, lane = tid & 31;
    int warpM = wid >> 1, warpN = wid & 1;
    int n0 = blockIdx.x * BN;

    const __nv_bfloat16* Ah = g_Sh + (size_t)row0 * HID;
    const __nv_bfloat16* Al = g_Sl + (size_t)row0 * HID;
    const __nv_bfloat16* Bh = g_W3h + (size_t)e * DIM * HID + (size_t)n0 * HID;
    const __nv_bfloat16* Bl = g_W3l + (size_t)e * DIM * HID + (size_t)n0 * HID;

    float acc[2][8][4];
#pragma unroll
    for (int a = 0; a < 2; a++)
#pragma unroll
        for (int b = 0; b < 8; b++)
#pragma unroll
            for (int c = 0; c < 4; c++) acc[a][b][c] = 0.0f;

    GEMM_MAINLOOP(HID / BK, HID)

    int qrow = lane >> 2, qcol = lane & 3;
#pragma unroll
    for (int mi = 0; mi < 2; mi++) {
        int rbase = row0 + warpM * 32 + mi * 16 + qrow;
#pragma unroll
        for (int half = 0; half < 2; half++) {
            int r = rbase + half * 8;
            int t = g_rowtok[r];
            if (t < 0) continue;
            float wgt = g_roww[r];
            float* orow = out + (size_t)t * DIM;
#pragma unroll
            for (int ni = 0; ni < 8; ni++) {
                int colg = blockIdx.x * BN + warpN * 64 + ni * 8 + qcol * 2;
                atomicAdd(orow + colg,     wgt * acc[mi][ni][half * 2]);
                atomicAdd(orow + colg + 1, wgt * acc[mi][ni][half * 2 + 1]);
            }
        }
    }
}

// ---------------- launch ----------------
extern "C" void kernel_launch(void* const* d_in, const int* in_sizes, int n_in,
                              void* d_out, int out_size) {
    const float* x  = (const float*)d_in[0];
    const float* Wg = (const float*)d_in[1];
    const float* W1 = (const float*)d_in[2];
    const float* W2 = (const float*)d_in[3];
    const float* W3 = (const float*)d_in[4];
    float* out = (float*)d_out;

    cudaFuncSetAttribute(k_gemm1, cudaFuncAttributeMaxDynamicSharedMemorySize, SMEMSZ);
    cudaFuncSetAttribute(k_gemm2, cudaFuncAttributeMaxDynamicSharedMemorySize, SMEMSZ);

    cudaMemsetAsync(out, 0, (size_t)T_TOK * DIM * sizeof(float));
    k_init<<<(RCAP + 255) / 256, 256>>>();
    k_gate<<<T_TOK / 8, 256>>>(x, Wg);
    k_offsets<<<1, 32>>>();
    k_scatter<<<(T_TOK * 2 + 255) / 256, 256>>>();
    k_gather<<<RCAP, 256>>>(x);
    k_tr12<<<dim3(HID / 32, DIM / 32, NE), dim3(32, 8)>>>(W1, 0);
    k_tr12<<<dim3(HID / 32, DIM / 32, NE), dim3(32, 8)>>>(W2, 1);
    k_tr3<<<dim3(DIM / 32, HID / 32, NE), dim3(32, 8)>>>(W3);

    k_gemm1<<<dim3(2 * HID / BN, RCAP / BM), 256, SMEMSZ>>>();
    k_gemm2<<<dim3(DIM / BN, RCAP / BM), 256, SMEMSZ>>>(out);
}